// round 1
// baseline (speedup 1.0000x reference)
#include <cuda_runtime.h>

#define DIM   480
#define SDIM  128
#define WPB   8      // warps (rows) per block
#define VECS  120    // DIM/4 float4 per row

__global__ __launch_bounds__(WPB * 32) void eqln_kernel(
    const float* __restrict__ x,
    const float* __restrict__ w,
    const float* __restrict__ bias,
    float* __restrict__ out,
    int n)
{
    __shared__ float buf[WPB][DIM];

    const int warp = threadIdx.x >> 5;
    const int lane = threadIdx.x & 31;
    const int row  = blockIdx.x * WPB + warp;
    if (row >= n) return;

    const size_t off = (size_t)row * DIM;

    // ---- cooperative vectorized load: 120 float4 (1920B, 16B-aligned) ----
    const float4* src = reinterpret_cast<const float4*>(x + off);
    float4* b4 = reinterpret_cast<float4*>(buf[warp]);
#pragma unroll
    for (int i = 0; i < 4; i++) {
        int idx = lane + i * 32;
        if (idx < VECS) b4[idx] = src[idx];
    }
    __syncwarp();

    // ---- layernorm over first 128 with weight/bias ----
    // lane owns elements [lane*4, lane*4+3] : conflict-free LDS.128 pattern
    float v0 = buf[warp][lane * 4 + 0];
    float v1 = buf[warp][lane * 4 + 1];
    float v2 = buf[warp][lane * 4 + 2];
    float v3 = buf[warp][lane * 4 + 3];
    float s  = v0 + v1 + v2 + v3;
    float ss = v0 * v0 + v1 * v1 + v2 * v2 + v3 * v3;
#pragma unroll
    for (int o = 16; o > 0; o >>= 1) {
        s  += __shfl_xor_sync(0xffffffffu, s,  o);
        ss += __shfl_xor_sync(0xffffffffu, ss, o);
    }
    const float mean = s * (1.0f / 128.0f);
    const float var  = ss * (1.0f / 128.0f) - mean * mean;
    const float rstd = rsqrtf(var + 1e-5f);
    {
        int c = lane * 4;
        buf[warp][c + 0] = (v0 - mean) * rstd * __ldg(w + c + 0) + __ldg(bias + c + 0);
        buf[warp][c + 1] = (v1 - mean) * rstd * __ldg(w + c + 1) + __ldg(bias + c + 1);
        buf[warp][c + 2] = (v2 - mean) * rstd * __ldg(w + c + 2) + __ldg(bias + c + 2);
        buf[warp][c + 3] = (v3 - mean) * rstd * __ldg(w + c + 3) + __ldg(bias + c + 3);
    }

    // ---- 64 segments of 3 (lane handles seg lane and lane+32) ----
    // stride-3 addresses: 3*l mod 32 is a permutation -> bank-conflict-free
#pragma unroll
    for (int k = 0; k < 2; k++) {
        int base = SDIM + (lane + k * 32) * 3;
        float a = buf[warp][base + 0];
        float b = buf[warp][base + 1];
        float c = buf[warp][base + 2];
        float m  = (a + b + c) * (1.0f / 3.0f);
        float da = a - m, db = b - m, dc = c - m;
        float rv = rsqrtf((da * da + db * db + dc * dc) * (1.0f / 3.0f) + 1e-5f);
        buf[warp][base + 0] = da * rv;
        buf[warp][base + 1] = db * rv;
        buf[warp][base + 2] = dc * rv;
    }

    // ---- 32 segments of 5 (lane handles seg lane) ----
    {
        int base = SDIM + 192 + lane * 5;
        float a = buf[warp][base + 0];
        float b = buf[warp][base + 1];
        float c = buf[warp][base + 2];
        float d = buf[warp][base + 3];
        float e = buf[warp][base + 4];
        float m  = (a + b + c + d + e) * 0.2f;
        float da = a - m, db = b - m, dc = c - m, dd = d - m, de = e - m;
        float rv = rsqrtf((da * da + db * db + dc * dc + dd * dd + de * de) * 0.2f + 1e-5f);
        buf[warp][base + 0] = da * rv;
        buf[warp][base + 1] = db * rv;
        buf[warp][base + 2] = dc * rv;
        buf[warp][base + 3] = dd * rv;
        buf[warp][base + 4] = de * rv;
    }
    __syncwarp();

    // ---- cooperative vectorized store ----
    float4* dst = reinterpret_cast<float4*>(out + off);
#pragma unroll
    for (int i = 0; i < 4; i++) {
        int idx = lane + i * 32;
        if (idx < VECS) dst[idx] = b4[idx];
    }
}

extern "C" void kernel_launch(void* const* d_in, const int* in_sizes, int n_in,
                              void* d_out, int out_size)
{
    const float* x    = (const float*)d_in[0];
    const float* w    = (const float*)d_in[1];
    const float* bias = (const float*)d_in[2];
    float* out        = (float*)d_out;

    int n = in_sizes[0] / DIM;          // number of rows
    int blocks = (n + WPB - 1) / WPB;
    eqln_kernel<<<blocks, WPB * 32>>>(x, w, bias, out, n);
}

// round 3
// speedup vs baseline: 1.0033x; 1.0033x over previous
#include <cuda_runtime.h>

#define DIM    480
#define SDIM   128
#define SEGF   352          // floats per row in smem (segments only: 128..479)
#define SEGV   88           // SEGF/4 float4
#define WPB    8            // warps (rows) per block

__global__ __launch_bounds__(WPB * 32) void eqln_kernel(
    const float* __restrict__ x,
    const float* __restrict__ w,
    const float* __restrict__ bias,
    float* __restrict__ out,
    int n)
{
    __shared__ float4 sbuf4[WPB][SEGV];   // only the segment region is staged

    const int warp = threadIdx.x >> 5;
    const int lane = threadIdx.x & 31;
    const int row  = blockIdx.x * WPB + warp;
    if (row >= n) return;

    float* sbuf = reinterpret_cast<float*>(sbuf4[warp]);
    const size_t off = (size_t)row * DIM;
    const float4* src = reinterpret_cast<const float4*>(x + off);
    float4* dst       = reinterpret_cast<float4*>(out + off);

    // ---- issue ALL global loads up front (max MLP) ----
    // LN region: vec idx == lane gives lane exactly floats 4l..4l+3 (register-resident)
    float4 q = __ldcs(src + lane);
    // segment region: vecs 32..119 staged cooperatively into smem
    float4 s0 = __ldcs(src + 32 + lane);
    float4 s1 = __ldcs(src + 64 + lane);
    float4 s2 = make_float4(0.f, 0.f, 0.f, 0.f);
    if (lane < SEGV - 64) s2 = __ldcs(src + 96 + lane);

    sbuf4[warp][lane]      = s0;
    sbuf4[warp][lane + 32] = s1;
    if (lane < SEGV - 64) sbuf4[warp][lane + 64] = s2;

    // ---- LayerNorm over first 128 — pure registers, overlaps the STS drain ----
    float s  = q.x + q.y + q.z + q.w;
    float ss = q.x * q.x + q.y * q.y + q.z * q.z + q.w * q.w;
#pragma unroll
    for (int o = 16; o > 0; o >>= 1) {
        s  += __shfl_xor_sync(0xffffffffu, s,  o);
        ss += __shfl_xor_sync(0xffffffffu, ss, o);
    }
    const float mean = s * (1.0f / 128.0f);
    const float var  = ss * (1.0f / 128.0f) - mean * mean;
    const float rstd = rsqrtf(var + 1e-5f);
    {
        const int c = lane * 4;
        float4 r;
        r.x = (q.x - mean) * rstd * __ldg(w + c + 0) + __ldg(bias + c + 0);
        r.y = (q.y - mean) * rstd * __ldg(w + c + 1) + __ldg(bias + c + 1);
        r.z = (q.z - mean) * rstd * __ldg(w + c + 2) + __ldg(bias + c + 2);
        r.w = (q.w - mean) * rstd * __ldg(w + c + 3) + __ldg(bias + c + 3);
        __stcs(dst + lane, r);              // direct coalesced store, no smem
    }

    __syncwarp();

    // ---- 64 segments of 3 (local offsets 0..191; stride-3 is bank-conflict-free) ----
#pragma unroll
    for (int k = 0; k < 2; k++) {
        int base = (lane + k * 32) * 3;
        float a = sbuf[base + 0];
        float b = sbuf[base + 1];
        float c = sbuf[base + 2];
        float m  = (a + b + c) * (1.0f / 3.0f);
        float da = a - m, db = b - m, dc = c - m;
        float rv = rsqrtf((da * da + db * db + dc * dc) * (1.0f / 3.0f) + 1e-5f);
        sbuf[base + 0] = da * rv;
        sbuf[base + 1] = db * rv;
        sbuf[base + 2] = dc * rv;
    }

    // ---- 32 segments of 5 (local offsets 192..351; stride-5 conflict-free) ----
    {
        int base = 192 + lane * 5;
        float a = sbuf[base + 0];
        float b = sbuf[base + 1];
        float c = sbuf[base + 2];
        float d = sbuf[base + 3];
        float e = sbuf[base + 4];
        float m  = (a + b + c + d + e) * 0.2f;
        float da = a - m, db = b - m, dc = c - m, dd = d - m, de = e - m;
        float rv = rsqrtf((da * da + db * db + dc * dc + dd * dd + de * de) * 0.2f + 1e-5f);
        sbuf[base + 0] = da * rv;
        sbuf[base + 1] = db * rv;
        sbuf[base + 2] = dc * rv;
        sbuf[base + 3] = dd * rv;
        sbuf[base + 4] = de * rv;
    }

    __syncwarp();

    // ---- cooperative vectorized store of segment region ----
    __stcs(dst + 32 + lane,  sbuf4[warp][lane]);
    __stcs(dst + 64 + lane,  sbuf4[warp][lane + 32]);
    if (lane < SEGV - 64)
        __stcs(dst + 96 + lane, sbuf4[warp][lane + 64]);
}

extern "C" void kernel_launch(void* const* d_in, const int* in_sizes, int n_in,
                              void* d_out, int out_size)
{
    const float* x    = (const float*)d_in[0];
    const float* w    = (const float*)d_in[1];
    const float* bias = (const float*)d_in[2];
    float* out        = (float*)d_out;

    int n = in_sizes[0] / DIM;
    int blocks = (n + WPB - 1) / WPB;
    eqln_kernel<<<blocks, WPB * 32>>>(x, w, bias, out, n);
}